// round 8
// baseline (speedup 1.0000x reference)
#include <cuda_runtime.h>
#include <cuda_fp16.h>
#include <cstdint>

// ============================================================================
// SourceAwareContrastiveLoss, GB300 — base sm_103 ISA.
// R8: fp16 end-to-end GEMM (fp16 inputs + fp16 accumulate, m16n8k16) probing
// the 2x fp16-acc rate; inputs are N(0,1) so fp16 is MORE accurate than bf16.
// R7's 16-warp / two-pass cp.async pipeline otherwise unchanged.
//
// loss = -(1/N) sum_i (scale*img_i·(S_{c(i)} - text_i) - cnt_i*lse_i)/cnt_i
// lse_i = logsumexp_j scale*(img_i·text_j)
// ============================================================================

#define NROWS 8192
#define DDIM  512
#define NSRC  8
#define BM    128
#define BN2   256              // N columns per pass (2 x 128 tiles)
#define BK    64
#define KSTEPS (DDIM / BK)     // 8 K-steps per pass
#define NCHUNKS 16             // columns split into 16 chunks of 512
#define PASSES_PER_CHUNK 2     // 512 / 256
#define MAIN_THREADS 512
#define NSTAGES 3

#define TSTRIDE 144                    // 128 B data + 16 B pad (conflict-free ldmatrix)
#define TILEB   (128 * TSTRIDE)        // 18432 B per operand tile
#define STAGEB  (3 * TILEB)            // A + B0 + B1
#define SM_MAIN_BYTES (NSTAGES * STAGEB)   // 165888 B

#define SRC_BLKS 128                   // srcsum partial blocks (64 rows each)

// ---------------- device scratch (static: no runtime allocation) -----------
__device__ __half g_img_hf [NROWS * DDIM];   // scale * img, fp16
__device__ __half g_text_hf[NROWS * DDIM];
__device__ float g_Spart[SRC_BLKS * NSRC * DDIM];
__device__ float g_S[NSRC * DDIM];
__device__ int   g_cntPart[SRC_BLKS * NSRC];
__device__ int   g_cnt[NSRC];
__device__ float g_pmax[NROWS * NCHUNKS];
__device__ float g_psum[NROWS * NCHUNKS];
__device__ float g_ploss[1024];
__device__ int   g_lab64;

// ---------------- label handling --------------------------------------------
__global__ void detect_labels_kernel(const int* labs) {
    if (threadIdx.x == 0 && blockIdx.x == 0) {
        int is64 = 1;
        for (int i = 0; i < 256; i++)
            if (labs[2 * i + 1] != 0) { is64 = 0; break; }
        g_lab64 = is64;
    }
}

__device__ __forceinline__ int get_label(const void* p, int i) {
    int v = g_lab64 ? (int)((const long long*)p)[i] : ((const int*)p)[i];
    return (v < 0) ? 0 : (v >= NSRC ? NSRC - 1 : v);
}

// ---------------- PTX helpers ----------------------------------------------
__device__ __forceinline__ uint32_t smem_to_u32(const void* p) {
    uint32_t a;
    asm("{ .reg .u64 t; cvta.to.shared.u64 t, %1; cvt.u32.u64 %0, t; }"
        : "=r"(a) : "l"(p));
    return a;
}

#define CP_ASYNC16(saddr, gptr) \
    asm volatile("cp.async.cg.shared.global [%0], [%1], 16;" \
        :: "r"(saddr), "l"(gptr))
#define CP_COMMIT() asm volatile("cp.async.commit_group;")
#define CP_WAIT(n)  asm volatile("cp.async.wait_group %0;" :: "n"(n))

#define LDMATRIX_X4(r, addr) \
    asm volatile("ldmatrix.sync.aligned.m8n8.x4.shared.b16 {%0,%1,%2,%3}, [%4];" \
        : "=r"((r)[0]), "=r"((r)[1]), "=r"((r)[2]), "=r"((r)[3]) : "r"(addr))

// fp16 inputs, fp16 accumulate: D,C = 2 x .f16x2 regs
#define MMA16816F16(d, a, b) \
    asm volatile("mma.sync.aligned.m16n8k16.row.col.f16.f16.f16.f16 " \
        "{%0,%1}, {%2,%3,%4,%5}, {%6,%7}, {%0,%1};" \
        : "+r"((d)[0]), "+r"((d)[1]) \
        : "r"((a)[0]), "r"((a)[1]), "r"((a)[2]), "r"((a)[3]), \
          "r"((b)[0]), "r"((b)[1]))

// ---------------- prologue kernels ------------------------------------------

// one launch: convert img (scaled) and text to fp16, float4-vectorized
__global__ void convert_kernel(const float* __restrict__ img,
                               const float* __restrict__ text,
                               const float* __restrict__ scale_ptr) {
    const int total4 = NROWS * DDIM / 4;       // per tensor
    int i = blockIdx.x * blockDim.x + threadIdx.x;
    if (i < total4) {
        float s = *scale_ptr;
        float4 v = ((const float4*)img)[i];
        __half2 lo = __floats2half2_rn(s * v.x, s * v.y);
        __half2 hi = __floats2half2_rn(s * v.z, s * v.w);
        ((uint2*)g_img_hf)[i] = make_uint2(*(uint32_t*)&lo, *(uint32_t*)&hi);
    } else {
        int j = i - total4;
        if (j < total4) {
            float4 v = ((const float4*)text)[j];
            __half2 lo = __floats2half2_rn(v.x, v.y);
            __half2 hi = __floats2half2_rn(v.z, v.w);
            ((uint2*)g_text_hf)[j] = make_uint2(*(uint32_t*)&lo, *(uint32_t*)&hi);
        }
    }
}

// per-64-row partial class sums of text features (128 blocks, coalesced)
__global__ void srcsum_kernel(const float* __restrict__ text,
                              const void* __restrict__ labels) {
    __shared__ int slab[64];
    const int k = threadIdx.x;          // 512 threads, one feature column each
    const int r0 = blockIdx.x * 64;
    if (k < 64) slab[k] = get_label(labels, r0 + k);
    __syncthreads();
    float s[NSRC];
#pragma unroll
    for (int c = 0; c < NSRC; c++) s[c] = 0.f;
    for (int r = 0; r < 64; r++) {
        int lab = slab[r];
        float v = text[(r0 + r) * DDIM + k];
#pragma unroll
        for (int c = 0; c < NSRC; c++) s[c] += (lab == c) ? v : 0.f;
    }
#pragma unroll
    for (int c = 0; c < NSRC; c++)
        g_Spart[(blockIdx.x * NSRC + c) * DDIM + k] = s[c];
    if (k < NSRC) {
        int cnt = 0;
        for (int r = 0; r < 64; r++) cnt += (slab[r] == k);
        g_cntPart[blockIdx.x * NSRC + k] = cnt;
    }
}

// one warp per output element (4096 outputs), 4 partial loads per lane + shfl
__global__ void reduceS_kernel() {
    const int warp = threadIdx.x >> 5;
    const int lane = threadIdx.x & 31;
    const int out  = blockIdx.x * 8 + warp;    // 512 blocks x 8 warps = 4096
    float a = 0.f;
#pragma unroll
    for (int g = 0; g < 4; g++) {
        int p = g * 32 + lane;                 // 128 partials
        a += g_Spart[p * (NSRC * DDIM) + out];
    }
#pragma unroll
    for (int o = 16; o; o >>= 1) a += __shfl_xor_sync(0xffffffffu, a, o);
    if (lane == 0) g_S[out] = a;

    if (blockIdx.x == 0) {                     // counts: 8 outputs, warp w -> cnt[w]
        int c = 0;
#pragma unroll
        for (int g = 0; g < 4; g++)
            c += g_cntPart[(g * 32 + lane) * NSRC + warp];
#pragma unroll
        for (int o = 16; o; o >>= 1) c += __shfl_xor_sync(0xffffffffu, c, o);
        if (lane == 0) g_cnt[warp] = c;
    }
}

// ---------------- main fused GEMM + online logsumexp ------------------------

// issue cp.async for one BK=64 k-slice (A + 2 B tiles) into `stage`
__device__ __forceinline__ void load_tiles(uint32_t sb, int stage,
                                           int m0, int n0, int tid, int k0) {
#pragma unroll
    for (int i = 0; i < 6; i++) {
        int idx    = i * MAIN_THREADS + tid;  // 0..3071
        int tile   = idx >> 10;               // 0=A, 1=B0, 2=B1
        int within = idx & 1023;
        int row    = within >> 3;             // 0..127
        int c8     = within & 7;              // 16B chunks
        const __half* base = tile ? g_text_hf : g_img_hf;
        int grow = (tile ? (n0 + (tile - 1) * 128) : m0) + row;
        const __half* g = base + grow * DDIM + k0 + c8 * 8;
        uint32_t s = sb + stage * STAGEB + tile * TILEB + row * TSTRIDE + c8 * 16;
        CP_ASYNC16(s, g);
    }
}

// grid = 1024 CTAs: (mt 0..63) x (chunk 0..15); each CTA: 128 rows x 512 cols
// 16 warps: wm 0..3 (32-row strip), wn 0..3 (64-col strip of the 256)
__global__ void __launch_bounds__(MAIN_THREADS, 1)
gemm_lse_kernel() {
    extern __shared__ char smem[];
    uint32_t sb = smem_to_u32(smem);
    const int tid  = threadIdx.x;
    const int warp = tid >> 5;
    const int lane = tid & 31;
    const int wm = warp >> 2;           // 0..3  (M subtile)
    const int wn = warp & 3;            // 0..3  (64-col strip; tile u=wn>>1)
    const int mt    = blockIdx.x & 63;
    const int chunk = blockIdx.x >> 6;
    const int m0    = mt * BM;
    const int nbase = chunk * 512;
    const float NEG_INF = __int_as_float(0xff800000);

    // ldmatrix per-lane address offsets (within an operand tile)
    const int a_row = wm * 32 + (lane & 15);                           // + tm*16
    const uint32_t a_off = (uint32_t)(a_row * TSTRIDE + ((lane >> 4) << 4));
    const int b_row = (wn & 1) * 64 + (lane & 7) + (((lane >> 4) & 1) << 3); // + tn2*16
    const uint32_t b_off = (uint32_t)(b_row * TSTRIDE + (((lane >> 3) & 1) << 4));
    const uint32_t b_tile_off = (uint32_t)((1 + (wn >> 1)) * TILEB);

    // running per-row logsumexp state: [tm][half]
    float rm[2][2], rs[2][2];
#pragma unroll
    for (int a = 0; a < 2; a++)
#pragma unroll
        for (int b = 0; b < 2; b++) { rm[a][b] = NEG_INF; rs[a][b] = 0.f; }

    for (int tp = 0; tp < PASSES_PER_CHUNK; tp++) {
        const int n0 = nbase + tp * BN2;

        uint32_t acc[2][8][2];     // [tm][tn][half] packed f16x2 — 32 regs
#pragma unroll
        for (int i = 0; i < 2; i++)
#pragma unroll
            for (int j = 0; j < 8; j++)
#pragma unroll
                for (int q = 0; q < 2; q++) acc[i][j][q] = 0u;

        // all warps must be done with previous pass's stages before reloading
        __syncthreads();
        load_tiles(sb, 0, m0, n0, tid, 0);  CP_COMMIT();
        load_tiles(sb, 1, m0, n0, tid, BK); CP_COMMIT();

        for (int ks = 0; ks < KSTEPS; ks++) {
            CP_WAIT(1);            // stage ks resident
            __syncthreads();       // all warps finished compute(ks-1)
            if (ks + 2 < KSTEPS)
                load_tiles(sb, (ks + 2) % NSTAGES, m0, n0, tid, (ks + 2) * BK);
            CP_COMMIT();           // may be empty (keeps wait count uniform)

            const uint32_t tb = sb + (uint32_t)((ks % NSTAGES) * STAGEB);
#pragma unroll
            for (int ksub = 0; ksub < 4; ksub++) {
                const uint32_t koff = (uint32_t)(ksub * 32);  // 16 elems = 32 B
                uint32_t afrag[2][4];
#pragma unroll
                for (int tm = 0; tm < 2; tm++) {
                    uint32_t addr = tb + a_off + (uint32_t)(tm * 16 * TSTRIDE) + koff;
                    LDMATRIX_X4(afrag[tm], addr);
                }
                uint32_t bfrag[8][2];
#pragma unroll
                for (int tn2 = 0; tn2 < 4; tn2++) {
                    uint32_t addr = tb + b_tile_off + b_off
                                  + (uint32_t)(tn2 * 16 * TSTRIDE) + koff;
                    uint32_t r[4];
                    LDMATRIX_X4(r, addr);
                    bfrag[2 * tn2][0] = r[0];     bfrag[2 * tn2][1] = r[1];
                    bfrag[2 * tn2 + 1][0] = r[2]; bfrag[2 * tn2 + 1][1] = r[3];
                }
#pragma unroll
                for (int tm = 0; tm < 2; tm++)
#pragma unroll
                    for (int tn = 0; tn < 8; tn++)
                        MMA16816F16(acc[tm][tn], afrag[tm], bfrag[tn]);
            }
        }

        // epilogue: online per-row max/sumexp over this warp's 64 cols
#pragma unroll
        for (int tm = 0; tm < 2; tm++) {
#pragma unroll
            for (int half = 0; half < 2; half++) {
                float mx = NEG_INF;
                float2 v[8];
#pragma unroll
                for (int tn = 0; tn < 8; tn++) {
                    v[tn] = __half22float2(*(__half2*)&acc[tm][tn][half]);
                    mx = fmaxf(mx, fmaxf(v[tn].x, v[tn].y));
                }
                mx = fmaxf(mx, __shfl_xor_sync(0xffffffffu, mx, 1));
                mx = fmaxf(mx, __shfl_xor_sync(0xffffffffu, mx, 2));
                float nm = fmaxf(rm[tm][half], mx);
                float s = 0.f;
#pragma unroll
                for (int tn = 0; tn < 8; tn++) {
                    s += __expf(v[tn].x - nm);
                    s += __expf(v[tn].y - nm);
                }
                s += __shfl_xor_sync(0xffffffffu, s, 1);
                s += __shfl_xor_sync(0xffffffffu, s, 2);
                rs[tm][half] = rs[tm][half] * __expf(rm[tm][half] - nm) + s;
                rm[tm][half] = nm;
            }
        }
    }

    // merge the four N-warps (wn=0..3) per row and store chunk partials
    float* s_m = (float*)smem;            // [4][128] (reuse tile smem)
    float* s_s = s_m + 512;
    __syncthreads();
    if ((lane & 3) == 0) {
#pragma unroll
        for (int tm = 0; tm < 2; tm++)
#pragma unroll
            for (int half = 0; half < 2; half++) {
                int row = wm * 32 + tm * 16 + half * 8 + (lane >> 2);
                s_m[wn * 128 + row] = rm[tm][half];
                s_s[wn * 128 + row] = rs[tm][half];
            }
    }
    __syncthreads();
    if (tid < BM) {
        float M = s_m[tid];
#pragma unroll
        for (int w = 1; w < 4; w++) M = fmaxf(M, s_m[w * 128 + tid]);
        float S = 0.f;
#pragma unroll
        for (int w = 0; w < 4; w++)
            S += s_s[w * 128 + tid] * __expf(s_m[w * 128 + tid] - M);
        g_pmax[(m0 + tid) * NCHUNKS + chunk] = M;
        g_psum[(m0 + tid) * NCHUNKS + chunk] = S;
    }
}

// ---------------- per-row finalize ------------------------------------------
__global__ void finalize_rows(const float* __restrict__ img,
                              const float* __restrict__ text,
                              const void* __restrict__ labels,
                              const float* __restrict__ scale_ptr) {
    const int warp = threadIdx.x >> 5;
    const int lane = threadIdx.x & 31;
    const int row  = blockIdx.x * 8 + warp;
    const float scale = *scale_ptr;
    const int c = get_label(labels, row);
    const int cnt = g_cnt[c] - 1;

    float pm = (lane < NCHUNKS) ? g_pmax[row * NCHUNKS + lane] : __int_as_float(0xff800000);
    float M = pm;
#pragma unroll
    for (int o = 16; o; o >>= 1) M = fmaxf(M, __shfl_xor_sync(0xffffffffu, M, o));
    float ps = (lane < NCHUNKS) ? g_psum[row * NCHUNKS + lane] * __expf(pm - M) : 0.f;
#pragma unroll
    for (int o = 16; o; o >>= 1) ps += __shfl_xor_sync(0xffffffffu, ps, o);
    float lse = M + __logf(ps);

    // exact fp32 masked-sum dot: img_row · (S_c - text_row), float4 loads
    const float4* img4  = (const float4*)(img  + row * DDIM);
    const float4* txt4  = (const float4*)(text + row * DDIM);
    const float4* Sc4   = (const float4*)(g_S + c * DDIM);
    float d = 0.f;
#pragma unroll
    for (int g = 0; g < DDIM / 128; g++) {
        int k = g * 32 + lane;
        float4 a = img4[k], b = txt4[k], s4 = Sc4[k];
        d += a.x * (s4.x - b.x) + a.y * (s4.y - b.y)
           + a.z * (s4.z - b.z) + a.w * (s4.w - b.w);
    }
#pragma unroll
    for (int o = 16; o; o >>= 1) d += __shfl_xor_sync(0xffffffffu, d, o);

    __shared__ float sh[8];
    if (lane == 0)
        sh[warp] = (cnt > 0) ? (scale * d - (float)cnt * lse) / (float)cnt : 0.f;
    __syncthreads();
    if (threadIdx.x == 0) {
        float a = 0.f;
#pragma unroll
        for (int w = 0; w < 8; w++) a += sh[w];
        g_ploss[blockIdx.x] = a;
    }
}

__global__ void final_reduce(float* __restrict__ out) {
    __shared__ float sh[256];
    float a = 0.f;
    for (int i = threadIdx.x; i < 1024; i += 256) a += g_ploss[i];
    sh[threadIdx.x] = a;
    __syncthreads();
    for (int s = 128; s; s >>= 1) {
        if (threadIdx.x < s) sh[threadIdx.x] += sh[threadIdx.x + s];
        __syncthreads();
    }
    if (threadIdx.x == 0) out[0] = -sh[0] / (float)NROWS;
}

// ---------------- launch ----------------------------------------------------
extern "C" void kernel_launch(void* const* d_in, const int* in_sizes, int n_in,
                              void* d_out, int out_size) {
    // Identify inputs by element count (robust to metadata ordering).
    const float* img   = nullptr;
    const float* text  = nullptr;
    const float* scale = nullptr;
    const void*  labels = nullptr;
    for (int i = 0; i < n_in; i++) {
        int s = in_sizes[i];
        if (s == NROWS * DDIM) {
            if (!img) img = (const float*)d_in[i];
            else      text = (const float*)d_in[i];
        } else if (s == 1) {
            scale = (const float*)d_in[i];
        } else if (s == NROWS) {
            labels = d_in[i];
        }
    }
    float* out = (float*)d_out;

    cudaFuncSetAttribute(gemm_lse_kernel,
                         cudaFuncAttributeMaxDynamicSharedMemorySize, SM_MAIN_BYTES);

    // gemm only depends on convert; srcsum/reduceS only feed finalize.
    // Order keeps gemm_lse_kernel at the profiler's capture slot.
    detect_labels_kernel<<<1, 32>>>((const int*)labels);
    const int conv_threads = 2 * NROWS * DDIM / 4;
    convert_kernel<<<(conv_threads + 255) / 256, 256>>>(img, text, scale);
    srcsum_kernel<<<SRC_BLKS, 512>>>(text, labels);
    gemm_lse_kernel<<<1024, MAIN_THREADS, SM_MAIN_BYTES>>>();
    reduceS_kernel<<<512, 256>>>();
    finalize_rows<<<1024, 256>>>(img, text, labels, scale);
    final_reduce<<<1, 256>>>(out);
}

// round 9
// speedup vs baseline: 1.0677x; 1.0677x over previous
#include <cuda_runtime.h>
#include <cuda_bf16.h>
#include <cstdint>

// ============================================================================
// SourceAwareContrastiveLoss, GB300 — base sm_103 ISA.
// R9: bf16 engine (fp16-acc probe failed), BK=128 with 2-stage double buffer:
// half the sync points per CTA (16 -> 8), same prefetch byte-depth.
//
// loss = -(1/N) sum_i (scale*img_i·(S_{c(i)} - text_i) - cnt_i*lse_i)/cnt_i
// lse_i = logsumexp_j scale*(img_i·text_j)
// ============================================================================

#define NROWS 8192
#define DDIM  512
#define NSRC  8
#define BM    128
#define BN2   256              // N columns per pass (2 x 128 tiles)
#define BK    128
#define KSTEPS (DDIM / BK)     // 4 K-steps per pass
#define NCHUNKS 16             // columns split into 16 chunks of 512
#define PASSES_PER_CHUNK 2     // 512 / 256
#define MAIN_THREADS 512
#define NSTAGES 2

#define TSTRIDE 272                    // 256 B data + 16 B pad (conflict-free ldmatrix)
#define TILEB   (128 * TSTRIDE)        // 34816 B per operand tile
#define STAGEB  (3 * TILEB)            // A + B0 + B1 = 104448 B
#define SM_MAIN_BYTES (NSTAGES * STAGEB)   // 208896 B

#define SRC_BLKS 128                   // srcsum partial blocks (64 rows each)

// ---------------- device scratch (static: no runtime allocation) -----------
__device__ __nv_bfloat16 g_img_bf [NROWS * DDIM];   // scale * img, bf16
__device__ __nv_bfloat16 g_text_bf[NROWS * DDIM];
__device__ float g_Spart[SRC_BLKS * NSRC * DDIM];
__device__ float g_S[NSRC * DDIM];
__device__ int   g_cntPart[SRC_BLKS * NSRC];
__device__ int   g_cnt[NSRC];
__device__ float g_pmax[NROWS * NCHUNKS];
__device__ float g_psum[NROWS * NCHUNKS];
__device__ float g_ploss[1024];
__device__ int   g_lab64;

// ---------------- label handling --------------------------------------------
__global__ void detect_labels_kernel(const int* labs) {
    if (threadIdx.x == 0 && blockIdx.x == 0) {
        int is64 = 1;
        for (int i = 0; i < 256; i++)
            if (labs[2 * i + 1] != 0) { is64 = 0; break; }
        g_lab64 = is64;
    }
}

__device__ __forceinline__ int get_label(const void* p, int i) {
    int v = g_lab64 ? (int)((const long long*)p)[i] : ((const int*)p)[i];
    return (v < 0) ? 0 : (v >= NSRC ? NSRC - 1 : v);
}

// ---------------- PTX helpers ----------------------------------------------
__device__ __forceinline__ uint32_t smem_to_u32(const void* p) {
    uint32_t a;
    asm("{ .reg .u64 t; cvta.to.shared.u64 t, %1; cvt.u32.u64 %0, t; }"
        : "=r"(a) : "l"(p));
    return a;
}

#define CP_ASYNC16(saddr, gptr) \
    asm volatile("cp.async.cg.shared.global [%0], [%1], 16;" \
        :: "r"(saddr), "l"(gptr))
#define CP_COMMIT() asm volatile("cp.async.commit_group;")
#define CP_WAIT(n)  asm volatile("cp.async.wait_group %0;" :: "n"(n))

#define LDMATRIX_X4(r, addr) \
    asm volatile("ldmatrix.sync.aligned.m8n8.x4.shared.b16 {%0,%1,%2,%3}, [%4];" \
        : "=r"((r)[0]), "=r"((r)[1]), "=r"((r)[2]), "=r"((r)[3]) : "r"(addr))

#define MMA16816(d, a, b) \
    asm volatile("mma.sync.aligned.m16n8k16.row.col.f32.bf16.bf16.f32 " \
        "{%0,%1,%2,%3}, {%4,%5,%6,%7}, {%8,%9}, {%0,%1,%2,%3};" \
        : "+f"((d)[0]), "+f"((d)[1]), "+f"((d)[2]), "+f"((d)[3]) \
        : "r"((a)[0]), "r"((a)[1]), "r"((a)[2]), "r"((a)[3]), \
          "r"((b)[0]), "r"((b)[1]))

// ---------------- prologue kernels ------------------------------------------

// one launch: convert img (scaled) and text to bf16, float4-vectorized
__global__ void convert_kernel(const float* __restrict__ img,
                               const float* __restrict__ text,
                               const float* __restrict__ scale_ptr) {
    const int total4 = NROWS * DDIM / 4;       // per tensor
    int i = blockIdx.x * blockDim.x + threadIdx.x;
    if (i < total4) {
        float s = *scale_ptr;
        float4 v = ((const float4*)img)[i];
        __nv_bfloat162 lo = __floats2bfloat162_rn(s * v.x, s * v.y);
        __nv_bfloat162 hi = __floats2bfloat162_rn(s * v.z, s * v.w);
        ((uint2*)g_img_bf)[i] = make_uint2(*(uint32_t*)&lo, *(uint32_t*)&hi);
    } else {
        int j = i - total4;
        if (j < total4) {
            float4 v = ((const float4*)text)[j];
            __nv_bfloat162 lo = __floats2bfloat162_rn(v.x, v.y);
            __nv_bfloat162 hi = __floats2bfloat162_rn(v.z, v.w);
            ((uint2*)g_text_bf)[j] = make_uint2(*(uint32_t*)&lo, *(uint32_t*)&hi);
        }
    }
}

// per-64-row partial class sums of text features (128 blocks, coalesced)
__global__ void srcsum_kernel(const float* __restrict__ text,
                              const void* __restrict__ labels) {
    __shared__ int slab[64];
    const int k = threadIdx.x;          // 512 threads, one feature column each
    const int r0 = blockIdx.x * 64;
    if (k < 64) slab[k] = get_label(labels, r0 + k);
    __syncthreads();
    float s[NSRC];
#pragma unroll
    for (int c = 0; c < NSRC; c++) s[c] = 0.f;
    for (int r = 0; r < 64; r++) {
        int lab = slab[r];
        float v = text[(r0 + r) * DDIM + k];
#pragma unroll
        for (int c = 0; c < NSRC; c++) s[c] += (lab == c) ? v : 0.f;
    }
#pragma unroll
    for (int c = 0; c < NSRC; c++)
        g_Spart[(blockIdx.x * NSRC + c) * DDIM + k] = s[c];
    if (k < NSRC) {
        int cnt = 0;
        for (int r = 0; r < 64; r++) cnt += (slab[r] == k);
        g_cntPart[blockIdx.x * NSRC + k] = cnt;
    }
}

// one warp per output element (4096 outputs), 4 partial loads per lane + shfl
__global__ void reduceS_kernel() {
    const int warp = threadIdx.x >> 5;
    const int lane = threadIdx.x & 31;
    const int out  = blockIdx.x * 8 + warp;    // 512 blocks x 8 warps = 4096
    float a = 0.f;
#pragma unroll
    for (int g = 0; g < 4; g++) {
        int p = g * 32 + lane;                 // 128 partials
        a += g_Spart[p * (NSRC * DDIM) + out];
    }
#pragma unroll
    for (int o = 16; o; o >>= 1) a += __shfl_xor_sync(0xffffffffu, a, o);
    if (lane == 0) g_S[out] = a;

    if (blockIdx.x == 0) {                     // counts: 8 outputs, warp w -> cnt[w]
        int c = 0;
#pragma unroll
        for (int g = 0; g < 4; g++)
            c += g_cntPart[(g * 32 + lane) * NSRC + warp];
#pragma unroll
        for (int o = 16; o; o >>= 1) c += __shfl_xor_sync(0xffffffffu, c, o);
        if (lane == 0) g_cnt[warp] = c;
    }
}

// ---------------- main fused GEMM + online logsumexp ------------------------

// issue cp.async for one BK=128 k-slice (A + 2 B tiles) into `stage`
__device__ __forceinline__ void load_tiles(uint32_t sb, int stage,
                                           int m0, int n0, int tid, int k0) {
#pragma unroll
    for (int i = 0; i < 12; i++) {
        int idx    = i * MAIN_THREADS + tid;  // 0..6143
        int tile   = idx >> 11;               // 0=A, 1=B0, 2=B1
        int within = idx & 2047;
        int row    = within >> 4;             // 0..127
        int c16    = within & 15;             // 16B chunks (256 B per row)
        const __nv_bfloat16* base = tile ? g_text_bf : g_img_bf;
        int grow = (tile ? (n0 + (tile - 1) * 128) : m0) + row;
        const __nv_bfloat16* g = base + grow * DDIM + k0 + c16 * 8;
        uint32_t s = sb + stage * STAGEB + tile * TILEB + row * TSTRIDE + c16 * 16;
        CP_ASYNC16(s, g);
    }
}

// grid = 1024 CTAs: (mt 0..63) x (chunk 0..15); each CTA: 128 rows x 512 cols
// 16 warps: wm 0..3 (32-row strip), wn 0..3 (64-col strip of the 256)
__global__ void __launch_bounds__(MAIN_THREADS, 1)
gemm_lse_kernel() {
    extern __shared__ char smem[];
    uint32_t sb = smem_to_u32(smem);
    const int tid  = threadIdx.x;
    const int warp = tid >> 5;
    const int lane = tid & 31;
    const int wm = warp >> 2;           // 0..3  (M subtile)
    const int wn = warp & 3;            // 0..3  (64-col strip; tile u=wn>>1)
    const int mt    = blockIdx.x & 63;
    const int chunk = blockIdx.x >> 6;
    const int m0    = mt * BM;
    const int nbase = chunk * 512;
    const float NEG_INF = __int_as_float(0xff800000);

    // ldmatrix per-lane address offsets (within an operand tile)
    const int a_row = wm * 32 + (lane & 15);                           // + tm*16
    const uint32_t a_off = (uint32_t)(a_row * TSTRIDE + ((lane >> 4) << 4));
    const int b_row = (wn & 1) * 64 + (lane & 7) + (((lane >> 4) & 1) << 3); // + tn2*16
    const uint32_t b_off = (uint32_t)(b_row * TSTRIDE + (((lane >> 3) & 1) << 4));
    const uint32_t b_tile_off = (uint32_t)((1 + (wn >> 1)) * TILEB);

    // running per-row logsumexp state: [tm][half]
    float rm[2][2], rs[2][2];
#pragma unroll
    for (int a = 0; a < 2; a++)
#pragma unroll
        for (int b = 0; b < 2; b++) { rm[a][b] = NEG_INF; rs[a][b] = 0.f; }

    for (int tp = 0; tp < PASSES_PER_CHUNK; tp++) {
        const int n0 = nbase + tp * BN2;

        float acc[2][8][4];        // [tm][tn][q] — 64 regs
#pragma unroll
        for (int i = 0; i < 2; i++)
#pragma unroll
            for (int j = 0; j < 8; j++)
#pragma unroll
                for (int q = 0; q < 4; q++) acc[i][j][q] = 0.f;

        // all warps must be done with previous pass's stages before reloading
        __syncthreads();
        load_tiles(sb, 0, m0, n0, tid, 0);  CP_COMMIT();

#pragma unroll
        for (int ks = 0; ks < KSTEPS; ks++) {
            CP_WAIT(0);            // stage ks resident (its group is the only pending)
            __syncthreads();       // all warps done reading stage (ks+1)&1 (step ks-1)
            if (ks + 1 < KSTEPS) {
                load_tiles(sb, (ks + 1) & 1, m0, n0, tid, (ks + 1) * BK);
                CP_COMMIT();       // overlaps with this step's compute
            }

            const uint32_t tb = sb + (uint32_t)((ks & 1) * STAGEB);
#pragma unroll
            for (int ksub = 0; ksub < 8; ksub++) {
                const uint32_t koff = (uint32_t)(ksub * 32);  // 16 elems = 32 B
                uint32_t afrag[2][4];
#pragma unroll
                for (int tm = 0; tm < 2; tm++) {
                    uint32_t addr = tb + a_off + (uint32_t)(tm * 16 * TSTRIDE) + koff;
                    LDMATRIX_X4(afrag[tm], addr);
                }
                uint32_t bfrag[8][2];
#pragma unroll
                for (int tn2 = 0; tn2 < 4; tn2++) {
                    uint32_t addr = tb + b_tile_off + b_off
                                  + (uint32_t)(tn2 * 16 * TSTRIDE) + koff;
                    uint32_t r[4];
                    LDMATRIX_X4(r, addr);
                    bfrag[2 * tn2][0] = r[0];     bfrag[2 * tn2][1] = r[1];
                    bfrag[2 * tn2 + 1][0] = r[2]; bfrag[2 * tn2 + 1][1] = r[3];
                }
#pragma unroll
                for (int tm = 0; tm < 2; tm++)
#pragma unroll
                    for (int tn = 0; tn < 8; tn++)
                        MMA16816(acc[tm][tn], afrag[tm], bfrag[tn]);
            }
        }

        // epilogue: online per-row max/sumexp over this warp's 64 cols
#pragma unroll
        for (int tm = 0; tm < 2; tm++) {
#pragma unroll
            for (int half = 0; half < 2; half++) {
                float mx = NEG_INF;
#pragma unroll
                for (int tn = 0; tn < 8; tn++)
                    mx = fmaxf(mx, fmaxf(acc[tm][tn][half * 2],
                                         acc[tm][tn][half * 2 + 1]));
                mx = fmaxf(mx, __shfl_xor_sync(0xffffffffu, mx, 1));
                mx = fmaxf(mx, __shfl_xor_sync(0xffffffffu, mx, 2));
                float nm = fmaxf(rm[tm][half], mx);
                float s = 0.f;
#pragma unroll
                for (int tn = 0; tn < 8; tn++) {
                    s += __expf(acc[tm][tn][half * 2]     - nm);
                    s += __expf(acc[tm][tn][half * 2 + 1] - nm);
                }
                s += __shfl_xor_sync(0xffffffffu, s, 1);
                s += __shfl_xor_sync(0xffffffffu, s, 2);
                rs[tm][half] = rs[tm][half] * __expf(rm[tm][half] - nm) + s;
                rm[tm][half] = nm;
            }
        }
    }

    // merge the four N-warps (wn=0..3) per row and store chunk partials
    float* s_m = (float*)smem;            // [4][128] (reuse tile smem)
    float* s_s = s_m + 512;
    __syncthreads();
    if ((lane & 3) == 0) {
#pragma unroll
        for (int tm = 0; tm < 2; tm++)
#pragma unroll
            for (int half = 0; half < 2; half++) {
                int row = wm * 32 + tm * 16 + half * 8 + (lane >> 2);
                s_m[wn * 128 + row] = rm[tm][half];
                s_s[wn * 128 + row] = rs[tm][half];
            }
    }
    __syncthreads();
    if (tid < BM) {
        float M = s_m[tid];
#pragma unroll
        for (int w = 1; w < 4; w++) M = fmaxf(M, s_m[w * 128 + tid]);
        float S = 0.f;
#pragma unroll
        for (int w = 0; w < 4; w++)
            S += s_s[w * 128 + tid] * __expf(s_m[w * 128 + tid] - M);
        g_pmax[(m0 + tid) * NCHUNKS + chunk] = M;
        g_psum[(m0 + tid) * NCHUNKS + chunk] = S;
    }
}

// ---------------- per-row finalize ------------------------------------------
__global__ void finalize_rows(const float* __restrict__ img,
                              const float* __restrict__ text,
                              const void* __restrict__ labels,
                              const float* __restrict__ scale_ptr) {
    const int warp = threadIdx.x >> 5;
    const int lane = threadIdx.x & 31;
    const int row  = blockIdx.x * 8 + warp;
    const float scale = *scale_ptr;
    const int c = get_label(labels, row);
    const int cnt = g_cnt[c] - 1;

    float pm = (lane < NCHUNKS) ? g_pmax[row * NCHUNKS + lane] : __int_as_float(0xff800000);
    float M = pm;
#pragma unroll
    for (int o = 16; o; o >>= 1) M = fmaxf(M, __shfl_xor_sync(0xffffffffu, M, o));
    float ps = (lane < NCHUNKS) ? g_psum[row * NCHUNKS + lane] * __expf(pm - M) : 0.f;
#pragma unroll
    for (int o = 16; o; o >>= 1) ps += __shfl_xor_sync(0xffffffffu, ps, o);
    float lse = M + __logf(ps);

    // exact fp32 masked-sum dot: img_row · (S_c - text_row), float4 loads
    const float4* img4  = (const float4*)(img  + row * DDIM);
    const float4* txt4  = (const float4*)(text + row * DDIM);
    const float4* Sc4   = (const float4*)(g_S + c * DDIM);
    float d = 0.f;
#pragma unroll
    for (int g = 0; g < DDIM / 128; g++) {
        int k = g * 32 + lane;
        float4 a = img4[k], b = txt4[k], s4 = Sc4[k];
        d += a.x * (s4.x - b.x) + a.y * (s4.y - b.y)
           + a.z * (s4.z - b.z) + a.w * (s4.w - b.w);
    }
#pragma unroll
    for (int o = 16; o; o >>= 1) d += __shfl_xor_sync(0xffffffffu, d, o);

    __shared__ float sh[8];
    if (lane == 0)
        sh[warp] = (cnt > 0) ? (scale * d - (float)cnt * lse) / (float)cnt : 0.f;
    __syncthreads();
    if (threadIdx.x == 0) {
        float a = 0.f;
#pragma unroll
        for (int w = 0; w < 8; w++) a += sh[w];
        g_ploss[blockIdx.x] = a;
    }
}

__global__ void final_reduce(float* __restrict__ out) {
    __shared__ float sh[256];
    float a = 0.f;
    for (int i = threadIdx.x; i < 1024; i += 256) a += g_ploss[i];
    sh[threadIdx.x] = a;
    __syncthreads();
    for (int s = 128; s; s >>= 1) {
        if (threadIdx.x < s) sh[threadIdx.x] += sh[threadIdx.x + s];
        __syncthreads();
    }
    if (threadIdx.x == 0) out[0] = -sh[0] / (float)NROWS;
}

// ---------------- launch ----------------------------------------------------
extern "C" void kernel_launch(void* const* d_in, const int* in_sizes, int n_in,
                              void* d_out, int out_size) {
    // Identify inputs by element count (robust to metadata ordering).
    const float* img   = nullptr;
    const float* text  = nullptr;
    const float* scale = nullptr;
    const void*  labels = nullptr;
    for (int i = 0; i < n_in; i++) {
        int s = in_sizes[i];
        if (s == NROWS * DDIM) {
            if (!img) img = (const float*)d_in[i];
            else      text = (const float*)d_in[i];
        } else if (s == 1) {
            scale = (const float*)d_in[i];
        } else if (s == NROWS) {
            labels = d_in[i];
        }
    }
    float* out = (float*)d_out;

    cudaFuncSetAttribute(gemm_lse_kernel,
                         cudaFuncAttributeMaxDynamicSharedMemorySize, SM_MAIN_BYTES);

    // gemm only depends on convert; srcsum/reduceS only feed finalize.
    // Order keeps gemm_lse_kernel at the profiler's capture slot.
    detect_labels_kernel<<<1, 32>>>((const int*)labels);
    const int conv_threads = 2 * NROWS * DDIM / 4;
    convert_kernel<<<(conv_threads + 255) / 256, 256>>>(img, text, scale);
    srcsum_kernel<<<SRC_BLKS, 512>>>(text, labels);
    gemm_lse_kernel<<<1024, MAIN_THREADS, SM_MAIN_BYTES>>>();
    reduceS_kernel<<<512, 256>>>();
    finalize_rows<<<1024, 256>>>(img, text, labels, scale);
    final_reduce<<<1, 256>>>(out);
}

// round 10
// speedup vs baseline: 1.1122x; 1.0417x over previous
#include <cuda_runtime.h>
#include <cuda_bf16.h>
#include <cstdint>

// ============================================================================
// SourceAwareContrastiveLoss, GB300 — base sm_103 ISA.
// R10: TWO CTAs per SM (__launch_bounds__(256,2), 110.6 KB smem each,
// 128 regs/thread) so one CTA's MMA stream covers the other's barrier /
// cp.async / epilogue phases. 8-warp 128x128-pass bf16 engine (R4 shape).
//
// loss = -(1/N) sum_i (scale*img_i·(S_{c(i)} - text_i) - cnt_i*lse_i)/cnt_i
// lse_i = logsumexp_j scale*(img_i·text_j)
// ============================================================================

#define NROWS 8192
#define DDIM  512
#define NSRC  8
#define BM    128
#define BN    128
#define BK    64
#define KSTEPS (DDIM / BK)     // 8 K-steps per pass
#define NCHUNKS 16             // columns split into 16 chunks of 512
#define TILES_PER_CHUNK 4      // 512 / 128
#define MAIN_THREADS 256
#define NSTAGES 3

#define TSTRIDE 144                    // 128 B data + 16 B pad (conflict-free ldmatrix)
#define TILEB   (128 * TSTRIDE)        // 18432 B per operand tile
#define STAGEB  (2 * TILEB)            // A + B
#define SM_MAIN_BYTES (NSTAGES * STAGEB)   // 110592 B  (x2 CTAs = 221184 <= 228KB)

#define SRC_BLKS 128                   // srcsum partial blocks (64 rows each)

// ---------------- device scratch (static: no runtime allocation) -----------
__device__ __nv_bfloat16 g_img_bf [NROWS * DDIM];   // scale * img, bf16
__device__ __nv_bfloat16 g_text_bf[NROWS * DDIM];
__device__ float g_Spart[SRC_BLKS * NSRC * DDIM];
__device__ float g_S[NSRC * DDIM];
__device__ int   g_cntPart[SRC_BLKS * NSRC];
__device__ int   g_cnt[NSRC];
__device__ float g_pmax[NROWS * NCHUNKS];
__device__ float g_psum[NROWS * NCHUNKS];
__device__ float g_ploss[1024];
__device__ int   g_lab64;

// ---------------- label handling --------------------------------------------
__global__ void detect_labels_kernel(const int* labs) {
    if (threadIdx.x == 0 && blockIdx.x == 0) {
        int is64 = 1;
        for (int i = 0; i < 256; i++)
            if (labs[2 * i + 1] != 0) { is64 = 0; break; }
        g_lab64 = is64;
    }
}

__device__ __forceinline__ int get_label(const void* p, int i) {
    int v = g_lab64 ? (int)((const long long*)p)[i] : ((const int*)p)[i];
    return (v < 0) ? 0 : (v >= NSRC ? NSRC - 1 : v);
}

// ---------------- PTX helpers ----------------------------------------------
__device__ __forceinline__ uint32_t smem_to_u32(const void* p) {
    uint32_t a;
    asm("{ .reg .u64 t; cvta.to.shared.u64 t, %1; cvt.u32.u64 %0, t; }"
        : "=r"(a) : "l"(p));
    return a;
}

#define CP_ASYNC16(saddr, gptr) \
    asm volatile("cp.async.cg.shared.global [%0], [%1], 16;" \
        :: "r"(saddr), "l"(gptr))
#define CP_COMMIT() asm volatile("cp.async.commit_group;")
#define CP_WAIT(n)  asm volatile("cp.async.wait_group %0;" :: "n"(n))

#define LDMATRIX_X4(r, addr) \
    asm volatile("ldmatrix.sync.aligned.m8n8.x4.shared.b16 {%0,%1,%2,%3}, [%4];" \
        : "=r"((r)[0]), "=r"((r)[1]), "=r"((r)[2]), "=r"((r)[3]) : "r"(addr))

#define MMA16816(d, a, b) \
    asm volatile("mma.sync.aligned.m16n8k16.row.col.f32.bf16.bf16.f32 " \
        "{%0,%1,%2,%3}, {%4,%5,%6,%7}, {%8,%9}, {%0,%1,%2,%3};" \
        : "+f"((d)[0]), "+f"((d)[1]), "+f"((d)[2]), "+f"((d)[3]) \
        : "r"((a)[0]), "r"((a)[1]), "r"((a)[2]), "r"((a)[3]), \
          "r"((b)[0]), "r"((b)[1]))

// ---------------- prologue kernels ------------------------------------------

// one launch: convert img (scaled) and text to bf16, float4-vectorized
__global__ void convert_kernel(const float* __restrict__ img,
                               const float* __restrict__ text,
                               const float* __restrict__ scale_ptr) {
    const int total4 = NROWS * DDIM / 4;       // per tensor
    int i = blockIdx.x * blockDim.x + threadIdx.x;
    if (i < total4) {
        float s = *scale_ptr;
        float4 v = ((const float4*)img)[i];
        __nv_bfloat162 lo = __floats2bfloat162_rn(s * v.x, s * v.y);
        __nv_bfloat162 hi = __floats2bfloat162_rn(s * v.z, s * v.w);
        ((uint2*)g_img_bf)[i] = make_uint2(*(uint32_t*)&lo, *(uint32_t*)&hi);
    } else {
        int j = i - total4;
        if (j < total4) {
            float4 v = ((const float4*)text)[j];
            __nv_bfloat162 lo = __floats2bfloat162_rn(v.x, v.y);
            __nv_bfloat162 hi = __floats2bfloat162_rn(v.z, v.w);
            ((uint2*)g_text_bf)[j] = make_uint2(*(uint32_t*)&lo, *(uint32_t*)&hi);
        }
    }
}

// per-64-row partial class sums of text features (128 blocks, coalesced)
__global__ void srcsum_kernel(const float* __restrict__ text,
                              const void* __restrict__ labels) {
    __shared__ int slab[64];
    const int k = threadIdx.x;          // 512 threads, one feature column each
    const int r0 = blockIdx.x * 64;
    if (k < 64) slab[k] = get_label(labels, r0 + k);
    __syncthreads();
    float s[NSRC];
#pragma unroll
    for (int c = 0; c < NSRC; c++) s[c] = 0.f;
    for (int r = 0; r < 64; r++) {
        int lab = slab[r];
        float v = text[(r0 + r) * DDIM + k];
#pragma unroll
        for (int c = 0; c < NSRC; c++) s[c] += (lab == c) ? v : 0.f;
    }
#pragma unroll
    for (int c = 0; c < NSRC; c++)
        g_Spart[(blockIdx.x * NSRC + c) * DDIM + k] = s[c];
    if (k < NSRC) {
        int cnt = 0;
        for (int r = 0; r < 64; r++) cnt += (slab[r] == k);
        g_cntPart[blockIdx.x * NSRC + k] = cnt;
    }
}

// one warp per output element (4096 outputs), 4 partial loads per lane + shfl
__global__ void reduceS_kernel() {
    const int warp = threadIdx.x >> 5;
    const int lane = threadIdx.x & 31;
    const int out  = blockIdx.x * 8 + warp;    // 512 blocks x 8 warps = 4096
    float a = 0.f;
#pragma unroll
    for (int g = 0; g < 4; g++) {
        int p = g * 32 + lane;                 // 128 partials
        a += g_Spart[p * (NSRC * DDIM) + out];
    }
#pragma unroll
    for (int o = 16; o; o >>= 1) a += __shfl_xor_sync(0xffffffffu, a, o);
    if (lane == 0) g_S[out] = a;

    if (blockIdx.x == 0) {                     // counts: 8 outputs, warp w -> cnt[w]
        int c = 0;
#pragma unroll
        for (int g = 0; g < 4; g++)
            c += g_cntPart[(g * 32 + lane) * NSRC + warp];
#pragma unroll
        for (int o = 16; o; o >>= 1) c += __shfl_xor_sync(0xffffffffu, c, o);
        if (lane == 0) g_cnt[warp] = c;
    }
}

// ---------------- main fused GEMM + online logsumexp ------------------------

// issue cp.async for one BK=64 k-slice (A + B tiles) into `stage`
__device__ __forceinline__ void load_tiles(uint32_t sb, int stage,
                                           int m0, int n0, int tid, int k0) {
#pragma unroll
    for (int i = 0; i < 8; i++) {
        int idx    = i * MAIN_THREADS + tid;  // 0..2047
        int tile   = idx >> 10;               // 0=A, 1=B
        int within = idx & 1023;
        int row    = within >> 3;             // 0..127
        int c8     = within & 7;              // 16B chunks
        const __nv_bfloat16* base = tile ? g_text_bf : g_img_bf;
        int grow = (tile ? n0 : m0) + row;
        const __nv_bfloat16* g = base + grow * DDIM + k0 + c8 * 8;
        uint32_t s = sb + stage * STAGEB + tile * TILEB + row * TSTRIDE + c8 * 16;
        CP_ASYNC16(s, g);
    }
}

// grid = 1024 CTAs: (mt 0..63) x (chunk 0..15); each CTA: 128 rows x 512 cols
// 8 warps: wm 0..3 (32-row strip), wn 0..1 (64-col strip)
__global__ void __launch_bounds__(MAIN_THREADS, 2)
gemm_lse_kernel() {
    extern __shared__ char smem[];
    uint32_t sb = smem_to_u32(smem);
    const int tid  = threadIdx.x;
    const int warp = tid >> 5;
    const int lane = tid & 31;
    const int wm = warp >> 1;           // 0..3  (M subtile)
    const int wn = warp & 1;            // 0..1  (N subtile)
    const int mt    = blockIdx.x & 63;
    const int chunk = blockIdx.x >> 6;
    const int m0    = mt * BM;
    const int nbase = chunk * 512;
    const float NEG_INF = __int_as_float(0xff800000);

    // ldmatrix per-lane address offsets (within an operand tile)
    const int a_row = wm * 32 + (lane & 15);                           // + tm*16
    const uint32_t a_off = (uint32_t)(a_row * TSTRIDE + ((lane >> 4) << 4));
    const int b_row = wn * 64 + (lane & 7) + (((lane >> 4) & 1) << 3); // + tn2*16
    const uint32_t b_off = (uint32_t)(b_row * TSTRIDE + (((lane >> 3) & 1) << 4));

    // running per-row logsumexp state: [tm][half]
    float rm[2][2], rs[2][2];
#pragma unroll
    for (int a = 0; a < 2; a++)
#pragma unroll
        for (int b = 0; b < 2; b++) { rm[a][b] = NEG_INF; rs[a][b] = 0.f; }

    for (int t = 0; t < TILES_PER_CHUNK; t++) {
        const int n0 = nbase + t * BN;

        float acc[2][8][4];        // [tm][tn][q] — 64 regs
#pragma unroll
        for (int i = 0; i < 2; i++)
#pragma unroll
            for (int j = 0; j < 8; j++)
#pragma unroll
                for (int q = 0; q < 4; q++) acc[i][j][q] = 0.f;

        // all warps must be done with previous pass's stages before reloading
        __syncthreads();
        load_tiles(sb, 0, m0, n0, tid, 0);  CP_COMMIT();
        load_tiles(sb, 1, m0, n0, tid, BK); CP_COMMIT();

        for (int ks = 0; ks < KSTEPS; ks++) {
            CP_WAIT(1);            // stage ks resident
            __syncthreads();       // all warps finished compute(ks-1)
            if (ks + 2 < KSTEPS)
                load_tiles(sb, (ks + 2) % NSTAGES, m0, n0, tid, (ks + 2) * BK);
            CP_COMMIT();           // may be empty (keeps wait count uniform)

            const uint32_t tb = sb + (uint32_t)((ks % NSTAGES) * STAGEB);
#pragma unroll
            for (int ksub = 0; ksub < 4; ksub++) {
                const uint32_t koff = (uint32_t)(ksub * 32);  // 16 elems = 32 B
                uint32_t afrag[2][4];
#pragma unroll
                for (int tm = 0; tm < 2; tm++) {
                    uint32_t addr = tb + a_off + (uint32_t)(tm * 16 * TSTRIDE) + koff;
                    LDMATRIX_X4(afrag[tm], addr);
                }
                uint32_t bfrag[8][2];
#pragma unroll
                for (int tn2 = 0; tn2 < 4; tn2++) {
                    uint32_t addr = tb + TILEB + b_off
                                  + (uint32_t)(tn2 * 16 * TSTRIDE) + koff;
                    uint32_t r[4];
                    LDMATRIX_X4(r, addr);
                    bfrag[2 * tn2][0] = r[0];     bfrag[2 * tn2][1] = r[1];
                    bfrag[2 * tn2 + 1][0] = r[2]; bfrag[2 * tn2 + 1][1] = r[3];
                }
#pragma unroll
                for (int tm = 0; tm < 2; tm++)
#pragma unroll
                    for (int tn = 0; tn < 8; tn++)
                        MMA16816(acc[tm][tn], afrag[tm], bfrag[tn]);
            }
        }

        // epilogue: online per-row max/sumexp over this 128-col tile
#pragma unroll
        for (int tm = 0; tm < 2; tm++) {
#pragma unroll
            for (int half = 0; half < 2; half++) {
                float mx = NEG_INF;
#pragma unroll
                for (int tn = 0; tn < 8; tn++)
                    mx = fmaxf(mx, fmaxf(acc[tm][tn][half * 2],
                                         acc[tm][tn][half * 2 + 1]));
                mx = fmaxf(mx, __shfl_xor_sync(0xffffffffu, mx, 1));
                mx = fmaxf(mx, __shfl_xor_sync(0xffffffffu, mx, 2));
                float nm = fmaxf(rm[tm][half], mx);
                float s = 0.f;
#pragma unroll
                for (int tn = 0; tn < 8; tn++) {
                    s += __expf(acc[tm][tn][half * 2]     - nm);
                    s += __expf(acc[tm][tn][half * 2 + 1] - nm);
                }
                s += __shfl_xor_sync(0xffffffffu, s, 1);
                s += __shfl_xor_sync(0xffffffffu, s, 2);
                rs[tm][half] = rs[tm][half] * __expf(rm[tm][half] - nm) + s;
                rm[tm][half] = nm;
            }
        }
    }

    // merge the two N-warps (wn=0/1) per row and store chunk partials
    float* s_m = (float*)smem;            // [2][128] (reuse tile smem)
    float* s_s = s_m + 256;
    __syncthreads();
    if ((lane & 3) == 0) {
#pragma unroll
        for (int tm = 0; tm < 2; tm++)
#pragma unroll
            for (int half = 0; half < 2; half++) {
                int row = wm * 32 + tm * 16 + half * 8 + (lane >> 2);
                s_m[wn * 128 + row] = rm[tm][half];
                s_s[wn * 128 + row] = rs[tm][half];
            }
    }
    __syncthreads();
    if (tid < BM) {
        float ma = s_m[tid], mb = s_m[128 + tid];
        float M = fmaxf(ma, mb);
        float S = s_s[tid] * __expf(ma - M) + s_s[128 + tid] * __expf(mb - M);
        g_pmax[(m0 + tid) * NCHUNKS + chunk] = M;
        g_psum[(m0 + tid) * NCHUNKS + chunk] = S;
    }
}

// ---------------- per-row finalize ------------------------------------------
__global__ void finalize_rows(const float* __restrict__ img,
                              const float* __restrict__ text,
                              const void* __restrict__ labels,
                              const float* __restrict__ scale_ptr) {
    const int warp = threadIdx.x >> 5;
    const int lane = threadIdx.x & 31;
    const int row  = blockIdx.x * 8 + warp;
    const float scale = *scale_ptr;
    const int c = get_label(labels, row);
    const int cnt = g_cnt[c] - 1;

    float pm = (lane < NCHUNKS) ? g_pmax[row * NCHUNKS + lane] : __int_as_float(0xff800000);
    float M = pm;
#pragma unroll
    for (int o = 16; o; o >>= 1) M = fmaxf(M, __shfl_xor_sync(0xffffffffu, M, o));
    float ps = (lane < NCHUNKS) ? g_psum[row * NCHUNKS + lane] * __expf(pm - M) : 0.f;
#pragma unroll
    for (int o = 16; o; o >>= 1) ps += __shfl_xor_sync(0xffffffffu, ps, o);
    float lse = M + __logf(ps);

    // exact fp32 masked-sum dot: img_row · (S_c - text_row), float4 loads
    const float4* img4  = (const float4*)(img  + row * DDIM);
    const float4* txt4  = (const float4*)(text + row * DDIM);
    const float4* Sc4   = (const float4*)(g_S + c * DDIM);
    float d = 0.f;
#pragma unroll
    for (int g = 0; g < DDIM / 128; g++) {
        int k = g * 32 + lane;
        float4 a = img4[k], b = txt4[k], s4 = Sc4[k];
        d += a.x * (s4.x - b.x) + a.y * (s4.y - b.y)
           + a.z * (s4.z - b.z) + a.w * (s4.w - b.w);
    }
#pragma unroll
    for (int o = 16; o; o >>= 1) d += __shfl_xor_sync(0xffffffffu, d, o);

    __shared__ float sh[8];
    if (lane == 0)
        sh[warp] = (cnt > 0) ? (scale * d - (float)cnt * lse) / (float)cnt : 0.f;
    __syncthreads();
    if (threadIdx.x == 0) {
        float a = 0.f;
#pragma unroll
        for (int w = 0; w < 8; w++) a += sh[w];
        g_ploss[blockIdx.x] = a;
    }
}

__global__ void final_reduce(float* __restrict__ out) {
    __shared__ float sh[256];
    float a = 0.f;
    for (int i = threadIdx.x; i < 1024; i += 256) a += g_ploss[i];
    sh[threadIdx.x] = a;
    __syncthreads();
    for (int s = 128; s; s >>= 1) {
        if (threadIdx.x < s) sh[threadIdx.x] += sh[threadIdx.x + s];
        __syncthreads();
    }
    if (threadIdx.x == 0) out[0] = -sh[0] / (float)NROWS;
}

// ---------------- launch ----------------------------------------------------
extern "C" void kernel_launch(void* const* d_in, const int* in_sizes, int n_in,
                              void* d_out, int out_size) {
    // Identify inputs by element count (robust to metadata ordering).
    const float* img   = nullptr;
    const float* text  = nullptr;
    const float* scale = nullptr;
    const void*  labels = nullptr;
    for (int i = 0; i < n_in; i++) {
        int s = in_sizes[i];
        if (s == NROWS * DDIM) {
            if (!img) img = (const float*)d_in[i];
            else      text = (const float*)d_in[i];
        } else if (s == 1) {
            scale = (const float*)d_in[i];
        } else if (s == NROWS) {
            labels = d_in[i];
        }
    }
    float* out = (float*)d_out;

    cudaFuncSetAttribute(gemm_lse_kernel,
                         cudaFuncAttributeMaxDynamicSharedMemorySize, SM_MAIN_BYTES);

    // gemm only depends on convert; srcsum/reduceS only feed finalize.
    // Order keeps gemm_lse_kernel at the profiler's capture slot.
    detect_labels_kernel<<<1, 32>>>((const int*)labels);
    const int conv_threads = 2 * NROWS * DDIM / 4;
    convert_kernel<<<(conv_threads + 255) / 256, 256>>>(img, text, scale);
    srcsum_kernel<<<SRC_BLKS, 512>>>(text, labels);
    gemm_lse_kernel<<<1024, MAIN_THREADS, SM_MAIN_BYTES>>>();
    reduceS_kernel<<<512, 256>>>();
    finalize_rows<<<1024, 256>>>(img, text, labels, scale);
    final_reduce<<<1, 256>>>(out);
}